// round 1
// baseline (speedup 1.0000x reference)
#include <cuda_runtime.h>

#define FULL 0xFFFFFFFFu

__device__ __forceinline__ float2 cmul(float2 a, float2 b) {
    return make_float2(fmaf(a.x, b.x, -a.y * b.y), fmaf(a.x, b.y, a.y * b.x));
}

// Column 0 of RZ(phi)*RY(pt)*RX(eta) applied to |0>:
//   after RX:  (cos e/2, -i sin e/2)
//   after RY:  b0 = (cy*ce, sy*se), b1 = (sy*ce, -cy*se)
//   after RZ:  u0 = e^{-i phi/2} b0, u1 = e^{+i phi/2} b1
__device__ __forceinline__ void wire_u(float pt, float eta, float phi,
                                       float2& u0, float2& u1) {
    float se, ce, sy, cy, sz, cz;
    __sincosf(0.5f * eta, &se, &ce);
    __sincosf(0.5f * pt, &sy, &cy);
    __sincosf(0.5f * phi, &sz, &cz);
    float2 b0 = make_float2(cy * ce, sy * se);
    float2 b1 = make_float2(sy * ce, -cy * se);
    u0 = cmul(make_float2(cz, -sz), b0);
    u1 = cmul(make_float2(cz, sz), b1);
}

// 4-qubit QAE block (ele / mu): latent=[0,1], trash=[2,3], depth=1.
// Wire k <-> amplitude bit (3-k). Whole 16-amp state in registers.
__device__ __forceinline__ void sim4(const float* __restrict__ xr,
                                     int pt_off, int eta_off, int phi_off,
                                     const float* __restrict__ w,
                                     float& o0, float& o1) {
    float2 u0[4], u1[4];
#pragma unroll
    for (int k = 0; k < 4; k++)
        wire_u(xr[pt_off + k], xr[eta_off + k], xr[phi_off + k], u0[k], u1[k]);

    // Encoding as tensor product (doubling over bits; bit j <-> wire 3-j)
    float2 a[16];
    a[0] = make_float2(1.f, 0.f);
#pragma unroll
    for (int j = 0; j < 4; j++) {
        int wk = 3 - j;
#pragma unroll
        for (int t = 0; t < (1 << j); t++) {
            a[t + (1 << j)] = cmul(a[t], u1[wk]);
            a[t]            = cmul(a[t], u0[wk]);
        }
    }

    // perm1: bits {3,2} ^= parity(bits {1,0})  (24->1 collapsed CNOT cascade)
    {
        float2 t;
        t = a[1];  a[1]  = a[13]; a[13] = t;
        t = a[2];  a[2]  = a[14]; a[14] = t;
        t = a[5];  a[5]  = a[9];  a[9]  = t;
        t = a[6];  a[6]  = a[10]; a[10] = t;
    }

    // RY(w[k]) on wire k (bit 3-k); RY is real -> x,y independent
#pragma unroll
    for (int k = 0; k < 4; k++) {
        float s, c;
        __sincosf(0.5f * w[k], &s, &c);
        int m = 1 << (3 - k);
#pragma unroll
        for (int i = 0; i < 16; i++) {
            if (!(i & m)) {
                int i1 = i | m;
                float2 a0 = a[i], a1v = a[i1];
                a[i]  = make_float2(c * a0.x - s * a1v.x, c * a0.y - s * a1v.y);
                a[i1] = make_float2(s * a0.x + c * a1v.x, s * a0.y + c * a1v.y);
            }
        }
    }

    // perm2: bits {1,0} ^= parity(bits {3,2})
    {
        float2 t;
        t = a[4]; a[4] = a[7];  a[7]  = t;
        t = a[5]; a[5] = a[6];  a[6]  = t;
        t = a[8]; a[8] = a[11]; a[11] = t;
        t = a[9]; a[9] = a[10]; a[10] = t;
    }

    // <Z> on trash wires 2 (bit1) and 3 (bit0)
    float r0 = 0.f, r1 = 0.f;
#pragma unroll
    for (int i = 0; i < 16; i++) {
        float p = fmaf(a[i].x, a[i].x, a[i].y * a[i].y);
        r0 += ((i >> 1) & 1) ? -p : p;
        r1 += (i & 1) ? -p : p;
    }
    o0 = r0;
    o1 = r1;
}

__global__ __launch_bounds__(256)
void qae_kernel(const float* __restrict__ x,
                const float* __restrict__ met_w,
                const float* __restrict__ ele_w,
                const float* __restrict__ mu_w,
                const float* __restrict__ jet_w,
                float* __restrict__ out,
                int B, int nJetBlocks) {
    if ((int)blockIdx.x < nJetBlocks) {
        // ---------------- jet block: one warp per event, n=10 qubits ----------------
        // amplitude index i (10 bits): lane = bits 0-4, register r = bits 5-9.
        // wire k <-> bit (9-k). latent wires 0-5 -> bits 9..4; trash 6-9 -> bits 3..0.
        int warp = blockIdx.x * 8 + (threadIdx.x >> 5);
        if (warp >= B) return;
        int lane = threadIdx.x & 31;
        const float* xr = x + (size_t)warp * 56;

        // per-wire encoding columns: lanes 0-9 compute, broadcast to all
        int kk = lane < 10 ? lane : 0;
        float2 myu0, myu1;
        wire_u(xr[26 + kk], xr[36 + kk], xr[46 + kk], myu0, myu1);
        float2 u0[10], u1[10];
#pragma unroll
        for (int k = 0; k < 10; k++) {
            u0[k].x = __shfl_sync(FULL, myu0.x, k);
            u0[k].y = __shfl_sync(FULL, myu0.y, k);
            u1[k].x = __shfl_sync(FULL, myu1.x, k);
            u1[k].y = __shfl_sync(FULL, myu1.y, k);
        }

        // lane-bit part of tensor product: lane bit m <-> wire 9-m
        float2 pl = make_float2(1.f, 0.f);
#pragma unroll
        for (int m = 0; m < 5; m++) {
            int w = 9 - m;
            float2 sel = ((lane >> m) & 1) ? u1[w] : u0[w];
            pl = cmul(pl, sel);
        }

        // register-bit part via doubling: r bit j <-> wire 4-j
        float2 a[32];
        a[0] = pl;
#pragma unroll
        for (int j = 0; j < 5; j++) {
            int w = 4 - j;
#pragma unroll
            for (int t = 0; t < (1 << j); t++) {
                a[t + (1 << j)] = cmul(a[t], u1[w]);
                a[t]            = cmul(a[t], u0[w]);
            }
        }

        int b4 = (lane >> 4) & 1;
        int p1 = __popc(lane & 15) & 1;  // parity of trash bits 3..0

#pragma unroll
        for (int d = 0; d < 4; d++) {
            // perm1: bits 9..4 ^= parity(bits 3..0)  => (lane^16, r^31) when p1
#pragma unroll
            for (int r = 0; r < 16; r++) {
                int r2 = r ^ 31;
                float tAx = __shfl_xor_sync(FULL, a[r].x, 16);
                float tAy = __shfl_xor_sync(FULL, a[r].y, 16);
                float tBx = __shfl_xor_sync(FULL, a[r2].x, 16);
                float tBy = __shfl_xor_sync(FULL, a[r2].y, 16);
                if (p1) {
                    a[r].x = tBx;  a[r].y = tBy;
                    a[r2].x = tAx; a[r2].y = tAy;
                }
            }
            // RY(jet_w[d*10+k]) on wire k (bit 9-k)
#pragma unroll
            for (int k = 0; k < 10; k++) {
                float s, c;
                __sincosf(0.5f * jet_w[d * 10 + k], &s, &c);
                int bit = 9 - k;
                if (bit >= 5) {  // register bit
                    int m = 1 << (bit - 5);
#pragma unroll
                    for (int r = 0; r < 32; r++) {
                        if (!(r & m)) {
                            int r1 = r | m;
                            float2 a0 = a[r], a1v = a[r1];
                            a[r]  = make_float2(c * a0.x - s * a1v.x,
                                                c * a0.y - s * a1v.y);
                            a[r1] = make_float2(s * a0.x + c * a1v.x,
                                                s * a0.y + c * a1v.y);
                        }
                    }
                } else {  // lane bit -> shfl_xor pairing
                    int m = 1 << bit;
                    float t = (lane & m) ? s : -s;
#pragma unroll
                    for (int r = 0; r < 32; r++) {
                        float px = __shfl_xor_sync(FULL, a[r].x, m);
                        float py = __shfl_xor_sync(FULL, a[r].y, m);
                        a[r].x = fmaf(t, px, c * a[r].x);
                        a[r].y = fmaf(t, py, c * a[r].y);
                    }
                }
            }
            // perm2: bits 3..0 ^= parity(bits 9..4) => lane^15 when q = popc(r)^b4
#pragma unroll
            for (int r = 0; r < 32; r++) {
                float px = __shfl_xor_sync(FULL, a[r].x, 15);
                float py = __shfl_xor_sync(FULL, a[r].y, 15);
                int q = (__popc(r) & 1) ^ b4;
                if (q) { a[r].x = px; a[r].y = py; }
            }
        }

        // <Z> on trash wires 6..9 (lane bits 3..0)
        float sacc = 0.f;
#pragma unroll
        for (int r = 0; r < 32; r++)
            sacc = fmaf(a[r].x, a[r].x, fmaf(a[r].y, a[r].y, sacc));
#pragma unroll
        for (int j = 0; j < 4; j++) {
            int bit = 3 - j;  // wire 6+j -> bit 3-j
            float v = ((lane >> bit) & 1) ? -sacc : sacc;
#pragma unroll
            for (int off = 16; off >= 1; off >>= 1)
                v += __shfl_xor_sync(FULL, v, off);
            if (lane == 0) out[(size_t)5 * B + (size_t)warp * 4 + j] = v;
        }
    } else {
        // ---------------- met + ele + mu: one thread per event ----------------
        int e = (blockIdx.x - nJetBlocks) * blockDim.x + threadIdx.x;
        if (e >= B) return;
        const float* xr = x + (size_t)e * 56;

        // met (n=1): <Z> = cos(w)cos(pt) - sin(w)sin(pt)cos(phi)
        {
            float sw, cw, sp, cp;
            __sincosf(met_w[0], &sw, &cw);
            __sincosf(xr[0], &sp, &cp);
            float cf = __cosf(xr[1]);
            out[e] = cw * cp - sw * sp * cf;
        }
        float o0, o1;
        sim4(xr, 2, 6, 10, ele_w, o0, o1);
        out[(size_t)B + (size_t)e * 2 + 0] = o0;
        out[(size_t)B + (size_t)e * 2 + 1] = o1;
        sim4(xr, 14, 18, 22, mu_w, o0, o1);
        out[(size_t)3 * B + (size_t)e * 2 + 0] = o0;
        out[(size_t)3 * B + (size_t)e * 2 + 1] = o1;
    }
}

extern "C" void kernel_launch(void* const* d_in, const int* in_sizes, int n_in,
                              void* d_out, int out_size) {
    const float* x     = (const float*)d_in[0];
    const float* met_w = (const float*)d_in[1];
    const float* ele_w = (const float*)d_in[2];
    const float* mu_w  = (const float*)d_in[3];
    const float* jet_w = (const float*)d_in[4];
    int B = in_sizes[0] / 56;
    int nJetBlocks = (B + 7) / 8;          // one warp per jet event, 8 warps/block
    int nSmallBlocks = (B + 255) / 256;    // one thread per event for met/ele/mu
    qae_kernel<<<nJetBlocks + nSmallBlocks, 256>>>(
        x, met_w, ele_w, mu_w, jet_w, (float*)d_out, B, nJetBlocks);
}

// round 2
// speedup vs baseline: 1.0006x; 1.0006x over previous
#include <cuda_runtime.h>

#define FULL 0xFFFFFFFFu

__device__ __forceinline__ float2 cmul(float2 a, float2 b) {
    return make_float2(fmaf(a.x, b.x, -a.y * b.y), fmaf(a.x, b.y, a.y * b.x));
}

// Column 0 of RZ(phi)*RY(pt)*RX(eta) applied to |0>:
//   after RX:  (cos e/2, -i sin e/2)
//   after RY:  b0 = (cy*ce, sy*se), b1 = (sy*ce, -cy*se)
//   after RZ:  u0 = e^{-i phi/2} b0, u1 = e^{+i phi/2} b1
__device__ __forceinline__ void wire_u(float pt, float eta, float phi,
                                       float2& u0, float2& u1) {
    float se, ce, sy, cy, sz, cz;
    __sincosf(0.5f * eta, &se, &ce);
    __sincosf(0.5f * pt, &sy, &cy);
    __sincosf(0.5f * phi, &sz, &cz);
    float2 b0 = make_float2(cy * ce, sy * se);
    float2 b1 = make_float2(sy * ce, -cy * se);
    u0 = cmul(make_float2(cz, -sz), b0);
    u1 = cmul(make_float2(cz, sz), b1);
}

// 4-qubit QAE block (ele / mu): latent=[0,1], trash=[2,3], depth=1.
// Wire k <-> amplitude bit (3-k). Whole 16-amp state in registers.
__device__ __forceinline__ void sim4(const float* __restrict__ xr,
                                     int pt_off, int eta_off, int phi_off,
                                     const float* __restrict__ w,
                                     float& o0, float& o1) {
    float2 u0[4], u1[4];
#pragma unroll
    for (int k = 0; k < 4; k++)
        wire_u(xr[pt_off + k], xr[eta_off + k], xr[phi_off + k], u0[k], u1[k]);

    // Encoding as tensor product (doubling over bits; bit j <-> wire 3-j)
    float2 a[16];
    a[0] = make_float2(1.f, 0.f);
#pragma unroll
    for (int j = 0; j < 4; j++) {
        int wk = 3 - j;
#pragma unroll
        for (int t = 0; t < (1 << j); t++) {
            a[t + (1 << j)] = cmul(a[t], u1[wk]);
            a[t]            = cmul(a[t], u0[wk]);
        }
    }

    // perm1: bits {3,2} ^= parity(bits {1,0})  (24->1 collapsed CNOT cascade)
    {
        float2 t;
        t = a[1];  a[1]  = a[13]; a[13] = t;
        t = a[2];  a[2]  = a[14]; a[14] = t;
        t = a[5];  a[5]  = a[9];  a[9]  = t;
        t = a[6];  a[6]  = a[10]; a[10] = t;
    }

    // RY(w[k]) on wire k (bit 3-k); RY is real -> x,y independent
#pragma unroll
    for (int k = 0; k < 4; k++) {
        float s, c;
        __sincosf(0.5f * w[k], &s, &c);
        int m = 1 << (3 - k);
#pragma unroll
        for (int i = 0; i < 16; i++) {
            if (!(i & m)) {
                int i1 = i | m;
                float2 a0 = a[i], a1v = a[i1];
                a[i]  = make_float2(c * a0.x - s * a1v.x, c * a0.y - s * a1v.y);
                a[i1] = make_float2(s * a0.x + c * a1v.x, s * a0.y + c * a1v.y);
            }
        }
    }

    // perm2: bits {1,0} ^= parity(bits {3,2})
    {
        float2 t;
        t = a[4]; a[4] = a[7];  a[7]  = t;
        t = a[5]; a[5] = a[6];  a[6]  = t;
        t = a[8]; a[8] = a[11]; a[11] = t;
        t = a[9]; a[9] = a[10]; a[10] = t;
    }

    // <Z> on trash wires 2 (bit1) and 3 (bit0)
    float r0 = 0.f, r1 = 0.f;
#pragma unroll
    for (int i = 0; i < 16; i++) {
        float p = fmaf(a[i].x, a[i].x, a[i].y * a[i].y);
        r0 += ((i >> 1) & 1) ? -p : p;
        r1 += (i & 1) ? -p : p;
    }
    o0 = r0;
    o1 = r1;
}

__global__ __launch_bounds__(256)
void qae_kernel(const float* __restrict__ x,
                const float* __restrict__ met_w,
                const float* __restrict__ ele_w,
                const float* __restrict__ mu_w,
                const float* __restrict__ jet_w,
                float* __restrict__ out,
                int B, int nJetBlocks) {
    if ((int)blockIdx.x < nJetBlocks) {
        // ---------------- jet block: one warp per event, n=10 qubits ----------------
        // amplitude index i (10 bits): lane = bits 0-4, register r = bits 5-9.
        // wire k <-> bit (9-k). latent wires 0-5 -> bits 9..4; trash 6-9 -> bits 3..0.
        int warp = blockIdx.x * 8 + (threadIdx.x >> 5);
        if (warp >= B) return;
        int lane = threadIdx.x & 31;
        const float* xr = x + (size_t)warp * 56;

        // per-wire encoding columns: lanes 0-9 compute, broadcast to all
        int kk = lane < 10 ? lane : 0;
        float2 myu0, myu1;
        wire_u(xr[26 + kk], xr[36 + kk], xr[46 + kk], myu0, myu1);
        float2 u0[10], u1[10];
#pragma unroll
        for (int k = 0; k < 10; k++) {
            u0[k].x = __shfl_sync(FULL, myu0.x, k);
            u0[k].y = __shfl_sync(FULL, myu0.y, k);
            u1[k].x = __shfl_sync(FULL, myu1.x, k);
            u1[k].y = __shfl_sync(FULL, myu1.y, k);
        }

        // lane-bit part of tensor product: lane bit m <-> wire 9-m
        float2 pl = make_float2(1.f, 0.f);
#pragma unroll
        for (int m = 0; m < 5; m++) {
            int w = 9 - m;
            float2 sel = ((lane >> m) & 1) ? u1[w] : u0[w];
            pl = cmul(pl, sel);
        }

        // register-bit part via doubling: r bit j <-> wire 4-j
        float2 a[32];
        a[0] = pl;
#pragma unroll
        for (int j = 0; j < 5; j++) {
            int w = 4 - j;
#pragma unroll
            for (int t = 0; t < (1 << j); t++) {
                a[t + (1 << j)] = cmul(a[t], u1[w]);
                a[t]            = cmul(a[t], u0[w]);
            }
        }

        int b4 = (lane >> 4) & 1;
        int p1 = __popc(lane & 15) & 1;  // parity of trash bits 3..0

#pragma unroll
        for (int d = 0; d < 4; d++) {
            // perm1: bits 9..4 ^= parity(bits 3..0)  => (lane^16, r^31) when p1
#pragma unroll
            for (int r = 0; r < 16; r++) {
                int r2 = r ^ 31;
                float tAx = __shfl_xor_sync(FULL, a[r].x, 16);
                float tAy = __shfl_xor_sync(FULL, a[r].y, 16);
                float tBx = __shfl_xor_sync(FULL, a[r2].x, 16);
                float tBy = __shfl_xor_sync(FULL, a[r2].y, 16);
                if (p1) {
                    a[r].x = tBx;  a[r].y = tBy;
                    a[r2].x = tAx; a[r2].y = tAy;
                }
            }
            // RY(jet_w[d*10+k]) on wire k (bit 9-k)
#pragma unroll
            for (int k = 0; k < 10; k++) {
                float s, c;
                __sincosf(0.5f * jet_w[d * 10 + k], &s, &c);
                int bit = 9 - k;
                if (bit >= 5) {  // register bit
                    int m = 1 << (bit - 5);
#pragma unroll
                    for (int r = 0; r < 32; r++) {
                        if (!(r & m)) {
                            int r1 = r | m;
                            float2 a0 = a[r], a1v = a[r1];
                            a[r]  = make_float2(c * a0.x - s * a1v.x,
                                                c * a0.y - s * a1v.y);
                            a[r1] = make_float2(s * a0.x + c * a1v.x,
                                                s * a0.y + c * a1v.y);
                        }
                    }
                } else {  // lane bit -> shfl_xor pairing
                    int m = 1 << bit;
                    float t = (lane & m) ? s : -s;
#pragma unroll
                    for (int r = 0; r < 32; r++) {
                        float px = __shfl_xor_sync(FULL, a[r].x, m);
                        float py = __shfl_xor_sync(FULL, a[r].y, m);
                        a[r].x = fmaf(t, px, c * a[r].x);
                        a[r].y = fmaf(t, py, c * a[r].y);
                    }
                }
            }
            // perm2: bits 3..0 ^= parity(bits 9..4) => lane^15 when q = popc(r)^b4
#pragma unroll
            for (int r = 0; r < 32; r++) {
                float px = __shfl_xor_sync(FULL, a[r].x, 15);
                float py = __shfl_xor_sync(FULL, a[r].y, 15);
                int q = (__popc(r) & 1) ^ b4;
                if (q) { a[r].x = px; a[r].y = py; }
            }
        }

        // <Z> on trash wires 6..9 (lane bits 3..0)
        float sacc = 0.f;
#pragma unroll
        for (int r = 0; r < 32; r++)
            sacc = fmaf(a[r].x, a[r].x, fmaf(a[r].y, a[r].y, sacc));
#pragma unroll
        for (int j = 0; j < 4; j++) {
            int bit = 3 - j;  // wire 6+j -> bit 3-j
            float v = ((lane >> bit) & 1) ? -sacc : sacc;
#pragma unroll
            for (int off = 16; off >= 1; off >>= 1)
                v += __shfl_xor_sync(FULL, v, off);
            if (lane == 0) out[(size_t)5 * B + (size_t)warp * 4 + j] = v;
        }
    } else {
        // ---------------- met + ele + mu: one thread per event ----------------
        int e = (blockIdx.x - nJetBlocks) * blockDim.x + threadIdx.x;
        if (e >= B) return;
        const float* xr = x + (size_t)e * 56;

        // met (n=1): <Z> = cos(w)cos(pt) - sin(w)sin(pt)cos(phi)
        {
            float sw, cw, sp, cp;
            __sincosf(met_w[0], &sw, &cw);
            __sincosf(xr[0], &sp, &cp);
            float cf = __cosf(xr[1]);
            out[e] = cw * cp - sw * sp * cf;
        }
        float o0, o1;
        sim4(xr, 2, 6, 10, ele_w, o0, o1);
        out[(size_t)B + (size_t)e * 2 + 0] = o0;
        out[(size_t)B + (size_t)e * 2 + 1] = o1;
        sim4(xr, 14, 18, 22, mu_w, o0, o1);
        out[(size_t)3 * B + (size_t)e * 2 + 0] = o0;
        out[(size_t)3 * B + (size_t)e * 2 + 1] = o1;
    }
}

extern "C" void kernel_launch(void* const* d_in, const int* in_sizes, int n_in,
                              void* d_out, int out_size) {
    const float* x     = (const float*)d_in[0];
    const float* met_w = (const float*)d_in[1];
    const float* ele_w = (const float*)d_in[2];
    const float* mu_w  = (const float*)d_in[3];
    const float* jet_w = (const float*)d_in[4];
    int B = in_sizes[0] / 56;
    int nJetBlocks = (B + 7) / 8;          // one warp per jet event, 8 warps/block
    int nSmallBlocks = (B + 255) / 256;    // one thread per event for met/ele/mu
    qae_kernel<<<nJetBlocks + nSmallBlocks, 256>>>(
        x, met_w, ele_w, mu_w, jet_w, (float*)d_out, B, nJetBlocks);
}

// round 3
// speedup vs baseline: 1.1976x; 1.1969x over previous
#include <cuda_runtime.h>

#define FULL 0xFFFFFFFFu
typedef unsigned long long ull;

// ---------- packed f32x2 helpers (Blackwell paired-FP32 path) ----------
__device__ __forceinline__ ull pack2(float x, float y) {
    ull r; asm("mov.b64 %0,{%1,%2};" : "=l"(r) : "f"(x), "f"(y)); return r;
}
__device__ __forceinline__ float2 unpack2(ull v) {
    float2 r; asm("mov.b64 {%0,%1},%2;" : "=f"(r.x), "=f"(r.y) : "l"(v)); return r;
}
__device__ __forceinline__ ull f2mul(ull a, ull b) {
    ull d; asm("mul.rn.f32x2 %0,%1,%2;" : "=l"(d) : "l"(a), "l"(b)); return d;
}
__device__ __forceinline__ ull f2fma(ull a, ull b, ull c) {  // a*b + c
    ull d; asm("fma.rn.f32x2 %0,%1,%2,%3;" : "=l"(d) : "l"(a), "l"(b), "l"(c)); return d;
}

__device__ __forceinline__ float2 cmul(float2 a, float2 b) {
    return make_float2(fmaf(a.x, b.x, -a.y * b.y), fmaf(a.x, b.y, a.y * b.x));
}

// Column 0 of RZ(phi)*RY(pt)*RX(eta) applied to |0>.
__device__ __forceinline__ void wire_u(float pt, float eta, float phi,
                                       float2& u0, float2& u1) {
    float se, ce, sy, cy, sz, cz;
    __sincosf(0.5f * eta, &se, &ce);
    __sincosf(0.5f * pt, &sy, &cy);
    __sincosf(0.5f * phi, &sz, &cz);
    float2 b0 = make_float2(cy * ce, sy * se);
    float2 b1 = make_float2(sy * ce, -cy * se);
    u0 = cmul(make_float2(cz, -sz), b0);
    u1 = cmul(make_float2(cz, sz), b1);
}

// 4-qubit QAE block (ele / mu): latent=[0,1], trash=[2,3], depth=1.
__device__ __forceinline__ void sim4(const float* __restrict__ xr,
                                     int pt_off, int eta_off, int phi_off,
                                     const float* __restrict__ w,
                                     float& o0, float& o1) {
    float2 u0[4], u1[4];
#pragma unroll
    for (int k = 0; k < 4; k++)
        wire_u(xr[pt_off + k], xr[eta_off + k], xr[phi_off + k], u0[k], u1[k]);

    float2 a[16];
    a[0] = make_float2(1.f, 0.f);
#pragma unroll
    for (int j = 0; j < 4; j++) {
        int wk = 3 - j;
#pragma unroll
        for (int t = 0; t < (1 << j); t++) {
            a[t + (1 << j)] = cmul(a[t], u1[wk]);
            a[t]            = cmul(a[t], u0[wk]);
        }
    }
    // perm1: bits {3,2} ^= parity(bits {1,0})
    {
        float2 t;
        t = a[1];  a[1]  = a[13]; a[13] = t;
        t = a[2];  a[2]  = a[14]; a[14] = t;
        t = a[5];  a[5]  = a[9];  a[9]  = t;
        t = a[6];  a[6]  = a[10]; a[10] = t;
    }
#pragma unroll
    for (int k = 0; k < 4; k++) {
        float s, c;
        __sincosf(0.5f * w[k], &s, &c);
        int m = 1 << (3 - k);
#pragma unroll
        for (int i = 0; i < 16; i++) {
            if (!(i & m)) {
                int i1 = i | m;
                float2 a0 = a[i], a1v = a[i1];
                a[i]  = make_float2(c * a0.x - s * a1v.x, c * a0.y - s * a1v.y);
                a[i1] = make_float2(s * a0.x + c * a1v.x, s * a0.y + c * a1v.y);
            }
        }
    }
    // perm2: bits {1,0} ^= parity(bits {3,2})
    {
        float2 t;
        t = a[4]; a[4] = a[7];  a[7]  = t;
        t = a[5]; a[5] = a[6];  a[6]  = t;
        t = a[8]; a[8] = a[11]; a[11] = t;
        t = a[9]; a[9] = a[10]; a[10] = t;
    }
    float r0 = 0.f, r1 = 0.f;
#pragma unroll
    for (int i = 0; i < 16; i++) {
        float p = fmaf(a[i].x, a[i].x, a[i].y * a[i].y);
        r0 += ((i >> 1) & 1) ? -p : p;
        r1 += (i & 1) ? -p : p;
    }
    o0 = r0;
    o1 = r1;
}

__global__ __launch_bounds__(256)
void qae_kernel(const float* __restrict__ x,
                const float* __restrict__ met_w,
                const float* __restrict__ ele_w,
                const float* __restrict__ mu_w,
                const float* __restrict__ jet_w,
                float* __restrict__ out,
                int B, int nJetBlocks) {
    if ((int)blockIdx.x < nJetBlocks) {
        // ================= jet: 2 events per warp, n=10 qubits =================
        // Amplitude index (10 bits): global bits 0..3 = lane bits (sub), trash
        // wires 9..6; global bits 4..9 = register bits r0..r5, latent wires 5..0.
        // Lane bit 4 selects which of the warp's two events this half handles.
        int warpId = blockIdx.x * 8 + (threadIdx.x >> 5);
        if (warpId * 2 >= B) return;
        int lane = threadIdx.x & 31;
        int sub  = lane & 15;
        int half = lane >> 4;
        int event = warpId * 2 + half;
        int evc = event < B ? event : B - 1;        // clamp loads for odd B
        const float* xr = x + (size_t)evc * 56;

        // Per-wire encoding columns: lanes sub 0..9 of each half compute; then
        // broadcast within the 16-lane half (width=16 shfl).
        int kk = sub < 10 ? sub : 0;
        float2 myu0, myu1;
        wire_u(xr[26 + kk], xr[36 + kk], xr[46 + kk], myu0, myu1);
        float2 u0[10], u1[10];
#pragma unroll
        for (int k = 0; k < 10; k++) {
            u0[k].x = __shfl_sync(FULL, myu0.x, k, 16);
            u0[k].y = __shfl_sync(FULL, myu0.y, k, 16);
            u1[k].x = __shfl_sync(FULL, myu1.x, k, 16);
            u1[k].y = __shfl_sync(FULL, myu1.y, k, 16);
        }

        // Lane-bit part of the tensor product: sub bit m <-> wire 9-m.
        float2 pl = make_float2(1.f, 0.f);
#pragma unroll
        for (int m = 0; m < 4; m++) {
            float2 sel = ((sub >> m) & 1) ? u1[9 - m] : u0[9 - m];
            pl = cmul(pl, sel);
        }

        // Register-bit part via doubling: reg bit j <-> wire 5-j.
        ull a[64];
        a[0] = pack2(pl.x, pl.y);
#pragma unroll
        for (int j = 0; j < 6; j++) {
            int w = 5 - j;
#pragma unroll
            for (int t = 0; t < (1 << j); t++) {
                float2 at = unpack2(a[t]);
                float2 hi = cmul(at, u1[w]);
                float2 lo = cmul(at, u0[w]);
                a[t + (1 << j)] = pack2(hi.x, hi.y);
                a[t]            = pack2(lo.x, lo.y);
            }
        }

        bool p1 = (__popc(sub) & 1) != 0;   // parity of trash bits

#pragma unroll 1
        for (int d = 0; d < 4; d++) {
            // perm1: flip all 6 register (latent) bits if p1 -> cond reg swap.
#pragma unroll
            for (int r = 0; r < 32; r++) {
                ull t0 = a[r], t1 = a[63 - r];
                a[r]      = p1 ? t1 : t0;
                a[63 - r] = p1 ? t0 : t1;
            }
            // RY(jet_w[d*10+k]) on wire k.
#pragma unroll
            for (int k = 0; k < 10; k++) {
                float s, c;
                __sincosf(0.5f * jet_w[d * 10 + k], &s, &c);
                ull c2 = pack2(c, c);
                if (k < 6) {                     // register bit j = 5-k
                    int m = 1 << (5 - k);
                    ull s2 = pack2(s, s), ns2 = pack2(-s, -s);
#pragma unroll
                    for (int r = 0; r < 64; r++) {
                        if (!(r & m)) {
                            int r1 = r | m;
                            ull a0 = a[r], a1v = a[r1];
                            a[r]  = f2fma(ns2, a1v, f2mul(c2, a0));
                            a[r1] = f2fma(s2, a0, f2mul(c2, a1v));
                        }
                    }
                } else {                         // lane bit (9-k): shfl pairing
                    int m = 1 << (9 - k);
                    float t = (sub & m) ? s : -s;
                    ull t2 = pack2(t, t);
#pragma unroll
                    for (int r = 0; r < 64; r++) {
                        ull p = __shfl_xor_sync(FULL, a[r], m);
                        a[r] = f2fma(t2, p, f2mul(c2, a[r]));
                    }
                }
            }
            // perm2: flip trash (lane) bits where popc(r) odd -> static per reg.
#pragma unroll
            for (int r = 0; r < 64; r++) {
                if (__popc(r) & 1)
                    a[r] = __shfl_xor_sync(FULL, a[r], 15);
            }
        }

        // <Z> on trash wires 6..9 (sub bits 3..0).
        ull acc2 = pack2(0.f, 0.f);
#pragma unroll
        for (int r = 0; r < 64; r++)
            acc2 = f2fma(a[r], a[r], acc2);
        float2 ac = unpack2(acc2);
        float sacc = ac.x + ac.y;
#pragma unroll
        for (int j = 0; j < 4; j++) {
            int bit = 3 - j;                 // wire 6+j -> sub bit 3-j
            float v = ((sub >> bit) & 1) ? -sacc : sacc;
#pragma unroll
            for (int off = 8; off >= 1; off >>= 1)
                v += __shfl_xor_sync(FULL, v, off);
            if (sub == 0 && event < B)
                out[(size_t)5 * B + (size_t)event * 4 + j] = v;
        }
    } else {
        // ---------------- met + ele + mu: one thread per event ----------------
        int e = (blockIdx.x - nJetBlocks) * blockDim.x + threadIdx.x;
        if (e >= B) return;
        const float* xr = x + (size_t)e * 56;

        {   // met (n=1): <Z> = cos(w)cos(pt) - sin(w)sin(pt)cos(phi)
            float sw, cw, sp, cp;
            __sincosf(met_w[0], &sw, &cw);
            __sincosf(xr[0], &sp, &cp);
            float cf = __cosf(xr[1]);
            out[e] = cw * cp - sw * sp * cf;
        }
        float o0, o1;
        sim4(xr, 2, 6, 10, ele_w, o0, o1);
        out[(size_t)B + (size_t)e * 2 + 0] = o0;
        out[(size_t)B + (size_t)e * 2 + 1] = o1;
        sim4(xr, 14, 18, 22, mu_w, o0, o1);
        out[(size_t)3 * B + (size_t)e * 2 + 0] = o0;
        out[(size_t)3 * B + (size_t)e * 2 + 1] = o1;
    }
}

extern "C" void kernel_launch(void* const* d_in, const int* in_sizes, int n_in,
                              void* d_out, int out_size) {
    const float* x     = (const float*)d_in[0];
    const float* met_w = (const float*)d_in[1];
    const float* ele_w = (const float*)d_in[2];
    const float* mu_w  = (const float*)d_in[3];
    const float* jet_w = (const float*)d_in[4];
    int B = in_sizes[0] / 56;
    int nJetBlocks = (B + 15) / 16;        // 8 warps/block, 2 events/warp
    int nSmallBlocks = (B + 255) / 256;    // 1 thread/event for met/ele/mu
    qae_kernel<<<nJetBlocks + nSmallBlocks, 256>>>(
        x, met_w, ele_w, mu_w, jet_w, (float*)d_out, B, nJetBlocks);
}

// round 4
// speedup vs baseline: 1.2531x; 1.0463x over previous
#include <cuda_runtime.h>

#define FULL 0xFFFFFFFFu
typedef unsigned long long ull;

// ---------- packed f32x2 helpers (Blackwell paired-FP32 path) ----------
__device__ __forceinline__ ull pack2(float x, float y) {
    ull r; asm("mov.b64 %0,{%1,%2};" : "=l"(r) : "f"(x), "f"(y)); return r;
}
__device__ __forceinline__ float2 unpack2(ull v) {
    float2 r; asm("mov.b64 {%0,%1},%2;" : "=f"(r.x), "=f"(r.y) : "l"(v)); return r;
}
__device__ __forceinline__ ull f2mul(ull a, ull b) {
    ull d; asm("mul.rn.f32x2 %0,%1,%2;" : "=l"(d) : "l"(a), "l"(b)); return d;
}
__device__ __forceinline__ ull f2fma(ull a, ull b, ull c) {  // a*b + c
    ull d; asm("fma.rn.f32x2 %0,%1,%2,%3;" : "=l"(d) : "l"(a), "l"(b), "l"(c)); return d;
}

__device__ __forceinline__ float2 cmul(float2 a, float2 b) {
    return make_float2(fmaf(a.x, b.x, -a.y * b.y), fmaf(a.x, b.y, a.y * b.x));
}

// Column 0 of RZ(phi)*RY(pt)*RX(eta) applied to |0>.
__device__ __forceinline__ void wire_u(float pt, float eta, float phi,
                                       float2& u0, float2& u1) {
    float se, ce, sy, cy, sz, cz;
    __sincosf(0.5f * eta, &se, &ce);
    __sincosf(0.5f * pt, &sy, &cy);
    __sincosf(0.5f * phi, &sz, &cz);
    float2 b0 = make_float2(cy * ce, sy * se);
    float2 b1 = make_float2(sy * ce, -cy * se);
    u0 = cmul(make_float2(cz, -sz), b0);
    u1 = cmul(make_float2(cz, sz), b1);
}

// width-16 broadcast of a float2 held lane-wise
__device__ __forceinline__ float2 bc16(float vx, float vy, int src) {
    float2 r;
    r.x = __shfl_sync(FULL, vx, src, 16);
    r.y = __shfl_sync(FULL, vy, src, 16);
    return r;
}

// 4-qubit QAE block (ele / mu): latent=[0,1], trash=[2,3], depth=1.
__device__ __forceinline__ void sim4(const float* __restrict__ xr,
                                     int pt_off, int eta_off, int phi_off,
                                     const float* __restrict__ w,
                                     float& o0, float& o1) {
    float2 u0[4], u1[4];
#pragma unroll
    for (int k = 0; k < 4; k++)
        wire_u(xr[pt_off + k], xr[eta_off + k], xr[phi_off + k], u0[k], u1[k]);

    float2 a[16];
    a[0] = make_float2(1.f, 0.f);
#pragma unroll
    for (int j = 0; j < 4; j++) {
        int wk = 3 - j;
#pragma unroll
        for (int t = 0; t < (1 << j); t++) {
            a[t + (1 << j)] = cmul(a[t], u1[wk]);
            a[t]            = cmul(a[t], u0[wk]);
        }
    }
    // perm1: bits {3,2} ^= parity(bits {1,0})
    {
        float2 t;
        t = a[1];  a[1]  = a[13]; a[13] = t;
        t = a[2];  a[2]  = a[14]; a[14] = t;
        t = a[5];  a[5]  = a[9];  a[9]  = t;
        t = a[6];  a[6]  = a[10]; a[10] = t;
    }
#pragma unroll
    for (int k = 0; k < 4; k++) {
        float s, c;
        __sincosf(0.5f * w[k], &s, &c);
        int m = 1 << (3 - k);
#pragma unroll
        for (int i = 0; i < 16; i++) {
            if (!(i & m)) {
                int i1 = i | m;
                float2 a0 = a[i], a1v = a[i1];
                a[i]  = make_float2(c * a0.x - s * a1v.x, c * a0.y - s * a1v.y);
                a[i1] = make_float2(s * a0.x + c * a1v.x, s * a0.y + c * a1v.y);
            }
        }
    }
    // perm2: bits {1,0} ^= parity(bits {3,2})
    {
        float2 t;
        t = a[4]; a[4] = a[7];  a[7]  = t;
        t = a[5]; a[5] = a[6];  a[6]  = t;
        t = a[8]; a[8] = a[11]; a[11] = t;
        t = a[9]; a[9] = a[10]; a[10] = t;
    }
    float r0 = 0.f, r1 = 0.f;
#pragma unroll
    for (int i = 0; i < 16; i++) {
        float p = fmaf(a[i].x, a[i].x, a[i].y * a[i].y);
        r0 += ((i >> 1) & 1) ? -p : p;
        r1 += (i & 1) ? -p : p;
    }
    o0 = r0;
    o1 = r1;
}

__global__ __launch_bounds__(128, 3)
void qae_kernel(const float* __restrict__ x,
                const float* __restrict__ met_w,
                const float* __restrict__ ele_w,
                const float* __restrict__ mu_w,
                const float* __restrict__ jet_w,
                float* __restrict__ out,
                int B, int nJetBlocks) {
    if ((int)blockIdx.x < nJetBlocks) {
        // ================= jet: 2 events per warp, n=10 qubits =================
        // Amplitude index (10 bits): global bits 0..3 = lane bits (sub), trash
        // wires 9..6; global bits 4..9 = register bits r0..r5, latent wires 5..0.
        // Lane bit 4 selects which of the warp's two events this half handles.
        int warpId = blockIdx.x * 4 + (threadIdx.x >> 5);
        if (warpId * 2 >= B) return;
        int lane = threadIdx.x & 31;
        int sub  = lane & 15;
        int half = lane >> 4;
        int event = warpId * 2 + half;
        int evc = event < B ? event : B - 1;        // clamp loads for odd B
        const float* xr = x + (size_t)evc * 56;

        // Per-wire encoding column: lanes sub 0..9 of each half compute; values
        // are broadcast on demand (no u[10] register arrays -> lower peak regs).
        int kk = sub < 10 ? sub : 0;
        float2 myu0, myu1;
        wire_u(xr[26 + kk], xr[36 + kk], xr[46 + kk], myu0, myu1);

        // Lane-bit part of the tensor product: sub bit m <-> wire 9-m.
        float2 pl = make_float2(1.f, 0.f);
#pragma unroll
        for (int m = 0; m < 4; m++) {
            int w = 9 - m;
            float2 b0 = bc16(myu0.x, myu0.y, w);
            float2 b1 = bc16(myu1.x, myu1.y, w);
            float2 sel = ((sub >> m) & 1) ? b1 : b0;
            pl = cmul(pl, sel);
        }

        // Register-bit part via doubling: reg bit j <-> wire 5-j.
        ull a[64];
        a[0] = pack2(pl.x, pl.y);
#pragma unroll
        for (int j = 0; j < 6; j++) {
            int w = 5 - j;
            float2 b0 = bc16(myu0.x, myu0.y, w);
            float2 b1 = bc16(myu1.x, myu1.y, w);
#pragma unroll
            for (int t = 0; t < (1 << j); t++) {
                float2 at = unpack2(a[t]);
                float2 hi = cmul(at, b1);
                float2 lo = cmul(at, b0);
                a[t + (1 << j)] = pack2(hi.x, hi.y);
                a[t]            = pack2(lo.x, lo.y);
            }
        }

        bool p1 = (__popc(sub) & 1) != 0;   // parity of trash bits

#pragma unroll 1
        for (int d = 0; d < 4; d++) {
            // perm1: flip all 6 register (latent) bits if p1 -> cond reg swap.
#pragma unroll
            for (int r = 0; r < 32; r++) {
                ull t0 = a[r], t1 = a[63 - r];
                a[r]      = p1 ? t1 : t0;
                a[63 - r] = p1 ? t0 : t1;
            }
            // RY(jet_w[d*10+k]) on wire k.
#pragma unroll
            for (int k = 0; k < 10; k++) {
                float s, c;
                __sincosf(0.5f * jet_w[d * 10 + k], &s, &c);
                ull c2 = pack2(c, c);
                if (k < 6) {                     // register bit j = 5-k
                    int m = 1 << (5 - k);
                    ull s2 = pack2(s, s), ns2 = pack2(-s, -s);
#pragma unroll
                    for (int r = 0; r < 64; r++) {
                        if (!(r & m)) {
                            int r1 = r | m;
                            ull a0 = a[r], a1v = a[r1];
                            a[r]  = f2fma(ns2, a1v, f2mul(c2, a0));
                            a[r1] = f2fma(s2, a0, f2mul(c2, a1v));
                        }
                    }
                } else {                         // lane bit (9-k): shfl pairing
                    int m = 1 << (9 - k);
                    float t = (sub & m) ? s : -s;
                    ull t2 = pack2(t, t);
#pragma unroll
                    for (int r = 0; r < 64; r++) {
                        ull p = __shfl_xor_sync(FULL, a[r], m);
                        a[r] = f2fma(t2, p, f2mul(c2, a[r]));
                    }
                }
            }
            // perm2: flip trash (lane) bits where popc(r) odd -> static per reg.
            // Skipped on the final depth: |a|^2 is permutation-invariant, so the
            // lane-bit flip is folded into the <Z> sign as (S_even - S_odd).
            if (d != 3) {
#pragma unroll
                for (int r = 0; r < 64; r++) {
                    if (__popc(r) & 1)
                        a[r] = __shfl_xor_sync(FULL, a[r], 15);
                }
            }
        }

        // <Z> on trash wires 6..9 (sub bits 3..0), with the skipped final perm2
        // absorbed: Z_b = sign_b(sub) * (S_evenparity - S_oddparity).
        ull ae = pack2(0.f, 0.f), ao = pack2(0.f, 0.f);
#pragma unroll
        for (int r = 0; r < 64; r++) {
            if (__popc(r) & 1) ao = f2fma(a[r], a[r], ao);
            else               ae = f2fma(a[r], a[r], ae);
        }
        float2 fe = unpack2(ae), fo = unpack2(ao);
        float sd = (fe.x + fe.y) - (fo.x + fo.y);
#pragma unroll
        for (int j = 0; j < 4; j++) {
            int bit = 3 - j;                 // wire 6+j -> sub bit 3-j
            float v = ((sub >> bit) & 1) ? -sd : sd;
#pragma unroll
            for (int off = 8; off >= 1; off >>= 1)
                v += __shfl_xor_sync(FULL, v, off);
            if (sub == 0 && event < B)
                out[(size_t)5 * B + (size_t)event * 4 + j] = v;
        }
    } else {
        // ---------------- met + ele + mu: one thread per event ----------------
        int e = (blockIdx.x - nJetBlocks) * 128 + threadIdx.x;
        if (e >= B) return;
        const float* xr = x + (size_t)e * 56;

        {   // met (n=1): <Z> = cos(w)cos(pt) - sin(w)sin(pt)cos(phi)
            float sw, cw, sp, cp;
            __sincosf(met_w[0], &sw, &cw);
            __sincosf(xr[0], &sp, &cp);
            float cf = __cosf(xr[1]);
            out[e] = cw * cp - sw * sp * cf;
        }
        float o0, o1;
        sim4(xr, 2, 6, 10, ele_w, o0, o1);
        out[(size_t)B + (size_t)e * 2 + 0] = o0;
        out[(size_t)B + (size_t)e * 2 + 1] = o1;
        sim4(xr, 14, 18, 22, mu_w, o0, o1);
        out[(size_t)3 * B + (size_t)e * 2 + 0] = o0;
        out[(size_t)3 * B + (size_t)e * 2 + 1] = o1;
    }
}

extern "C" void kernel_launch(void* const* d_in, const int* in_sizes, int n_in,
                              void* d_out, int out_size) {
    const float* x     = (const float*)d_in[0];
    const float* met_w = (const float*)d_in[1];
    const float* ele_w = (const float*)d_in[2];
    const float* mu_w  = (const float*)d_in[3];
    const float* jet_w = (const float*)d_in[4];
    int B = in_sizes[0] / 56;
    int nJetBlocks = (B + 7) / 8;          // 4 warps/block, 2 events/warp
    int nSmallBlocks = (B + 127) / 128;    // 1 thread/event for met/ele/mu
    qae_kernel<<<nJetBlocks + nSmallBlocks, 128>>>(
        x, met_w, ele_w, mu_w, jet_w, (float*)d_out, B, nJetBlocks);
}

// round 5
// speedup vs baseline: 1.5615x; 1.2462x over previous
#include <cuda_runtime.h>

#define FULL 0xFFFFFFFFu
typedef unsigned long long ull;

// ---------- packed f32x2 helpers (Blackwell paired-FP32 path) ----------
__device__ __forceinline__ ull pack2(float x, float y) {
    ull r; asm("mov.b64 %0,{%1,%2};" : "=l"(r) : "f"(x), "f"(y)); return r;
}
__device__ __forceinline__ float2 unpack2(ull v) {
    float2 r; asm("mov.b64 {%0,%1},%2;" : "=f"(r.x), "=f"(r.y) : "l"(v)); return r;
}
__device__ __forceinline__ ull f2fma(ull a, ull b, ull c) {  // a*b + c
    ull d; asm("fma.rn.f32x2 %0,%1,%2,%3;" : "=l"(d) : "l"(a), "l"(b), "l"(c)); return d;
}

__device__ __forceinline__ float2 cmul(float2 a, float2 b) {
    return make_float2(fmaf(a.x, b.x, -a.y * b.y), fmaf(a.x, b.y, a.y * b.x));
}

// Column 0 of RZ(phi)*RY(pt)*RX(eta) applied to |0>.
__device__ __forceinline__ void wire_u(float pt, float eta, float phi,
                                       float2& u0, float2& u1) {
    float se, ce, sy, cy, sz, cz;
    __sincosf(0.5f * eta, &se, &ce);
    __sincosf(0.5f * pt, &sy, &cy);
    __sincosf(0.5f * phi, &sz, &cz);
    float2 b0 = make_float2(cy * ce, sy * se);
    float2 b1 = make_float2(sy * ce, -cy * se);
    u0 = cmul(make_float2(cz, -sz), b0);
    u1 = cmul(make_float2(cz, sz), b1);
}

// width-16 broadcast of a float2 held lane-wise
__device__ __forceinline__ float2 bc16(float vx, float vy, int src) {
    float2 r;
    r.x = __shfl_sync(FULL, vx, src, 16);
    r.y = __shfl_sync(FULL, vy, src, 16);
    return r;
}

// 4-qubit QAE block (ele / mu): latent=[0,1], trash=[2,3], depth=1.
// RY gates use tau-factorization: RY = c*[[1,-tau],[tau,1]], scale folded into Z.
__device__ __forceinline__ void sim4(const float* __restrict__ xr,
                                     int pt_off, int eta_off, int phi_off,
                                     const float* __restrict__ w,
                                     float& o0, float& o1) {
    float2 u0[4], u1[4];
#pragma unroll
    for (int k = 0; k < 4; k++)
        wire_u(xr[pt_off + k], xr[eta_off + k], xr[phi_off + k], u0[k], u1[k]);

    float2 a[16];
    a[0] = make_float2(1.f, 0.f);
#pragma unroll
    for (int j = 0; j < 4; j++) {
        int wk = 3 - j;
#pragma unroll
        for (int t = 0; t < (1 << j); t++) {
            a[t + (1 << j)] = cmul(a[t], u1[wk]);
            a[t]            = cmul(a[t], u0[wk]);
        }
    }
    // perm1: bits {3,2} ^= parity(bits {1,0})
    {
        float2 t;
        t = a[1];  a[1]  = a[13]; a[13] = t;
        t = a[2];  a[2]  = a[14]; a[14] = t;
        t = a[5];  a[5]  = a[9];  a[9]  = t;
        t = a[6];  a[6]  = a[10]; a[10] = t;
    }
    float sc = 1.f;
#pragma unroll
    for (int k = 0; k < 4; k++) {
        float s, c;
        __sincosf(0.5f * w[k], &s, &c);
        float tau = __fdividef(s, c);
        sc *= c;
        int m = 1 << (3 - k);
#pragma unroll
        for (int i = 0; i < 16; i++) {
            if (!(i & m)) {
                int i1 = i | m;
                float2 a0 = a[i], a1v = a[i1];
                a[i]  = make_float2(fmaf(-tau, a1v.x, a0.x), fmaf(-tau, a1v.y, a0.y));
                a[i1] = make_float2(fmaf(tau, a0.x, a1v.x), fmaf(tau, a0.y, a1v.y));
            }
        }
    }
    // perm2: bits {1,0} ^= parity(bits {3,2})
    {
        float2 t;
        t = a[4]; a[4] = a[7];  a[7]  = t;
        t = a[5]; a[5] = a[6];  a[6]  = t;
        t = a[8]; a[8] = a[11]; a[11] = t;
        t = a[9]; a[9] = a[10]; a[10] = t;
    }
    float r0 = 0.f, r1 = 0.f;
#pragma unroll
    for (int i = 0; i < 16; i++) {
        float p = fmaf(a[i].x, a[i].x, a[i].y * a[i].y);
        r0 += ((i >> 1) & 1) ? -p : p;
        r1 += (i & 1) ? -p : p;
    }
    float sc2 = sc * sc;
    o0 = r0 * sc2;
    o1 = r1 * sc2;
}

__global__ __launch_bounds__(64, 5)
void qae_kernel(const float* __restrict__ x,
                const float* __restrict__ met_w,
                const float* __restrict__ ele_w,
                const float* __restrict__ mu_w,
                const float* __restrict__ jet_w,
                float* __restrict__ out,
                int B, int nJetBlocks) {
    if ((int)blockIdx.x < nJetBlocks) {
        // ================= jet: 2 events per warp, n=10 qubits =================
        // Amplitude index (10 bits): lane bits 0..3 (sub) = trash wires 9..6;
        // register bits r0..r5 = latent wires 5..0. Lane bit 4 = event select.
        int warpId = blockIdx.x * 2 + (threadIdx.x >> 5);
        if (warpId * 2 >= B) return;
        int lane = threadIdx.x & 31;
        int sub  = lane & 15;
        int half = lane >> 4;
        int event = warpId * 2 + half;
        int evc = event < B ? event : B - 1;        // clamp loads for odd B
        const float* xr = x + (size_t)evc * 56;

        // Per-wire encoding column: lanes sub 0..9 of each half compute; values
        // broadcast on demand via width-16 shfl.
        int kk = sub < 10 ? sub : 0;
        float2 myu0, myu1;
        wire_u(xr[26 + kk], xr[36 + kk], xr[46 + kk], myu0, myu1);

        // Lane-bit part of the tensor product: sub bit m <-> trash wire 9-m.
        float2 pl = make_float2(1.f, 0.f);
#pragma unroll
        for (int m = 0; m < 4; m++) {
            int w = 9 - m;
            float2 b0 = bc16(myu0.x, myu0.y, w);
            float2 b1 = bc16(myu1.x, myu1.y, w);
            float2 sel = ((sub >> m) & 1) ? b1 : b0;
            pl = cmul(pl, sel);
        }

        bool p1 = (__popc(sub) & 1) != 0;   // parity of trash bits

        // Register-bit part via doubling: reg bit j <-> latent wire 5-j.
        // Depth-0 perm1 (flip all latent bits if p1) folded in: u roles swap.
        ull a[64];
        a[0] = pack2(pl.x, pl.y);
#pragma unroll
        for (int j = 0; j < 6; j++) {
            int w = 5 - j;
            float2 b0 = bc16(myu0.x, myu0.y, w);
            float2 b1 = bc16(myu1.x, myu1.y, w);
            float2 f0 = p1 ? b1 : b0;
            float2 f1 = p1 ? b0 : b1;
#pragma unroll
            for (int t = 0; t < (1 << j); t++) {
                float2 at = unpack2(a[t]);
                float2 hi = cmul(at, f1);
                float2 lo = cmul(at, f0);
                a[t + (1 << j)] = pack2(hi.x, hi.y);
                a[t]            = pack2(lo.x, lo.y);
            }
        }

        float scw = 1.f;   // accumulated product of cos(theta/2) over all gates

#pragma unroll 1
        for (int d = 0; d < 4; d++) {
            // perm1 (d>0; depth-0 folded into encoding): flip all 6 register
            // (latent) bits if p1 -> conditional register-pair swap.
            if (d) {
#pragma unroll
                for (int r = 0; r < 32; r++) {
                    ull t0 = a[r], t1 = a[63 - r];
                    a[r]      = p1 ? t1 : t0;
                    a[63 - r] = p1 ? t0 : t1;
                }
            }
            // RY(jet_w[d*10+k]) on wire k, tau-factorized (scale deferred).
#pragma unroll
            for (int k = 0; k < 10; k++) {
                float s, c;
                __sincosf(0.5f * jet_w[d * 10 + k], &s, &c);
                float tau = __fdividef(s, c);
                scw *= c;
                if (k < 6) {                     // register bit j = 5-k
                    int m = 1 << (5 - k);
                    ull tq = pack2(tau, tau), ntq = pack2(-tau, -tau);
#pragma unroll
                    for (int r = 0; r < 64; r++) {
                        if (!(r & m)) {
                            int r1 = r | m;
                            ull a0 = a[r];
                            a[r]  = f2fma(ntq, a[r1], a0);
                            a[r1] = f2fma(tq, a0, a[r1]);
                        }
                    }
                } else {                         // lane bit (9-k): shfl pairing
                    int mb = 1 << (9 - k);
                    float tt = (sub & mb) ? tau : -tau;
                    ull t2 = pack2(tt, tt);
#pragma unroll
                    for (int r = 0; r < 64; r++) {
                        ull p = __shfl_xor_sync(FULL, a[r], mb);
                        a[r] = f2fma(t2, p, a[r]);
                    }
                }
            }
            // perm2: flip trash (lane) bits where popc(r) odd. Skipped on the
            // final depth (folded into the <Z> sign as S_even - S_odd).
            if (d != 3) {
#pragma unroll
                for (int r = 0; r < 64; r++) {
                    if (__popc(r) & 1)
                        a[r] = __shfl_xor_sync(FULL, a[r], 15);
                }
            }
        }

        // <Z> on trash wires 6..9 (sub bits 3..0), final perm2 + global scale
        // absorbed: Z_b = sign_b(sub) * (S_even - S_odd) * scw^2.
        ull ae = pack2(0.f, 0.f), ao = pack2(0.f, 0.f);
#pragma unroll
        for (int r = 0; r < 64; r++) {
            if (__popc(r) & 1) ao = f2fma(a[r], a[r], ao);
            else               ae = f2fma(a[r], a[r], ae);
        }
        float2 fe = unpack2(ae), fo = unpack2(ao);
        float sd = ((fe.x + fe.y) - (fo.x + fo.y)) * (scw * scw);
#pragma unroll
        for (int j = 0; j < 4; j++) {
            int bit = 3 - j;                 // wire 6+j -> sub bit 3-j
            float v = ((sub >> bit) & 1) ? -sd : sd;
#pragma unroll
            for (int off = 8; off >= 1; off >>= 1)
                v += __shfl_xor_sync(FULL, v, off);
            if (sub == 0 && event < B)
                out[(size_t)5 * B + (size_t)event * 4 + j] = v;
        }
    } else {
        // ---------------- met + ele + mu: one thread per event ----------------
        int e = (blockIdx.x - nJetBlocks) * 64 + threadIdx.x;
        if (e >= B) return;
        const float* xr = x + (size_t)e * 56;

        {   // met (n=1): <Z> = cos(w)cos(pt) - sin(w)sin(pt)cos(phi)
            float sw, cw, sp, cp;
            __sincosf(met_w[0], &sw, &cw);
            __sincosf(xr[0], &sp, &cp);
            float cf = __cosf(xr[1]);
            out[e] = cw * cp - sw * sp * cf;
        }
        float o0, o1;
        sim4(xr, 2, 6, 10, ele_w, o0, o1);
        out[(size_t)B + (size_t)e * 2 + 0] = o0;
        out[(size_t)B + (size_t)e * 2 + 1] = o1;
        sim4(xr, 14, 18, 22, mu_w, o0, o1);
        out[(size_t)3 * B + (size_t)e * 2 + 0] = o0;
        out[(size_t)3 * B + (size_t)e * 2 + 1] = o1;
    }
}

extern "C" void kernel_launch(void* const* d_in, const int* in_sizes, int n_in,
                              void* d_out, int out_size) {
    const float* x     = (const float*)d_in[0];
    const float* met_w = (const float*)d_in[1];
    const float* ele_w = (const float*)d_in[2];
    const float* mu_w  = (const float*)d_in[3];
    const float* jet_w = (const float*)d_in[4];
    int B = in_sizes[0] / 56;
    int nJetBlocks = (B + 3) / 4;          // 2 warps/block, 2 events/warp
    int nSmallBlocks = (B + 63) / 64;      // 1 thread/event for met/ele/mu
    qae_kernel<<<nJetBlocks + nSmallBlocks, 64>>>(
        x, met_w, ele_w, mu_w, jet_w, (float*)d_out, B, nJetBlocks);
}

// round 6
// speedup vs baseline: 1.5630x; 1.0010x over previous
#include <cuda_runtime.h>

#define FULL 0xFFFFFFFFu
typedef unsigned long long ull;

// Precomputed gate parameters (weights are batch-uniform):
//   g_tau[0..39]  = tan(jet_w/2),  g_tau[40..43] = tan(ele_w/2),
//   g_tau[44..47] = tan(mu_w/2)
//   g_scale[0..2] = (prod cos(w/2))^2 for jet / ele / mu
//   g_met[0..1]   = sin(met_w), cos(met_w)
__device__ float g_tau[48];
__device__ float g_scale[3];
__device__ float g_met[2];

__global__ void prep_kernel(const float* __restrict__ met_w,
                            const float* __restrict__ ele_w,
                            const float* __restrict__ mu_w,
                            const float* __restrict__ jet_w) {
    if (threadIdx.x == 0) {
        float p = 1.f;
        for (int i = 0; i < 40; i++) {
            float s, c; __sincosf(0.5f * jet_w[i], &s, &c);
            g_tau[i] = __fdividef(s, c); p *= c;
        }
        g_scale[0] = p * p;
        p = 1.f;
        for (int i = 0; i < 4; i++) {
            float s, c; __sincosf(0.5f * ele_w[i], &s, &c);
            g_tau[40 + i] = __fdividef(s, c); p *= c;
        }
        g_scale[1] = p * p;
        p = 1.f;
        for (int i = 0; i < 4; i++) {
            float s, c; __sincosf(0.5f * mu_w[i], &s, &c);
            g_tau[44 + i] = __fdividef(s, c); p *= c;
        }
        g_scale[2] = p * p;
        float s, c; __sincosf(met_w[0], &s, &c);
        g_met[0] = s; g_met[1] = c;
    }
}

// ---------- packed f32x2 helpers (Blackwell paired-FP32 path) ----------
__device__ __forceinline__ ull pack2(float x, float y) {
    ull r; asm("mov.b64 %0,{%1,%2};" : "=l"(r) : "f"(x), "f"(y)); return r;
}
__device__ __forceinline__ float2 unpack2(ull v) {
    float2 r; asm("mov.b64 {%0,%1},%2;" : "=f"(r.x), "=f"(r.y) : "l"(v)); return r;
}
__device__ __forceinline__ ull f2fma(ull a, ull b, ull c) {  // a*b + c
    ull d; asm("fma.rn.f32x2 %0,%1,%2,%3;" : "=l"(d) : "l"(a), "l"(b), "l"(c)); return d;
}

__device__ __forceinline__ float2 cmul(float2 a, float2 b) {
    return make_float2(fmaf(a.x, b.x, -a.y * b.y), fmaf(a.x, b.y, a.y * b.x));
}

// Column 0 of RZ(phi)*RY(pt)*RX(eta) applied to |0>.
__device__ __forceinline__ void wire_u(float pt, float eta, float phi,
                                       float2& u0, float2& u1) {
    float se, ce, sy, cy, sz, cz;
    __sincosf(0.5f * eta, &se, &ce);
    __sincosf(0.5f * pt, &sy, &cy);
    __sincosf(0.5f * phi, &sz, &cz);
    float2 b0 = make_float2(cy * ce, sy * se);
    float2 b1 = make_float2(sy * ce, -cy * se);
    u0 = cmul(make_float2(cz, -sz), b0);
    u1 = cmul(make_float2(cz, sz), b1);
}

// width-16 broadcast of a float2 held lane-wise
__device__ __forceinline__ float2 bc16(float vx, float vy, int src) {
    float2 r;
    r.x = __shfl_sync(FULL, vx, src, 16);
    r.y = __shfl_sync(FULL, vy, src, 16);
    return r;
}

// 4-qubit QAE block (ele / mu): latent=[0,1], trash=[2,3], depth=1.
// RY gates tau-factorized; overall scale (prod cos)^2 passed in.
__device__ __forceinline__ void sim4(const float* __restrict__ xr,
                                     int pt_off, int eta_off, int phi_off,
                                     const float* __restrict__ taus, float sc2,
                                     float& o0, float& o1) {
    float2 u0[4], u1[4];
#pragma unroll
    for (int k = 0; k < 4; k++)
        wire_u(xr[pt_off + k], xr[eta_off + k], xr[phi_off + k], u0[k], u1[k]);

    float2 a[16];
    a[0] = make_float2(1.f, 0.f);
#pragma unroll
    for (int j = 0; j < 4; j++) {
        int wk = 3 - j;
#pragma unroll
        for (int t = 0; t < (1 << j); t++) {
            a[t + (1 << j)] = cmul(a[t], u1[wk]);
            a[t]            = cmul(a[t], u0[wk]);
        }
    }
    // perm1: bits {3,2} ^= parity(bits {1,0})
    {
        float2 t;
        t = a[1];  a[1]  = a[13]; a[13] = t;
        t = a[2];  a[2]  = a[14]; a[14] = t;
        t = a[5];  a[5]  = a[9];  a[9]  = t;
        t = a[6];  a[6]  = a[10]; a[10] = t;
    }
#pragma unroll
    for (int k = 0; k < 4; k++) {
        float tau = taus[k];
        int m = 1 << (3 - k);
#pragma unroll
        for (int i = 0; i < 16; i++) {
            if (!(i & m)) {
                int i1 = i | m;
                float2 a0 = a[i], a1v = a[i1];
                a[i]  = make_float2(fmaf(-tau, a1v.x, a0.x), fmaf(-tau, a1v.y, a0.y));
                a[i1] = make_float2(fmaf(tau, a0.x, a1v.x), fmaf(tau, a0.y, a1v.y));
            }
        }
    }
    // perm2: bits {1,0} ^= parity(bits {3,2})
    {
        float2 t;
        t = a[4]; a[4] = a[7];  a[7]  = t;
        t = a[5]; a[5] = a[6];  a[6]  = t;
        t = a[8]; a[8] = a[11]; a[11] = t;
        t = a[9]; a[9] = a[10]; a[10] = t;
    }
    float r0 = 0.f, r1 = 0.f;
#pragma unroll
    for (int i = 0; i < 16; i++) {
        float p = fmaf(a[i].x, a[i].x, a[i].y * a[i].y);
        r0 += ((i >> 1) & 1) ? -p : p;
        r1 += (i & 1) ? -p : p;
    }
    o0 = r0 * sc2;
    o1 = r1 * sc2;
}

__global__ __launch_bounds__(64, 6)
void qae_kernel(const float* __restrict__ x,
                float* __restrict__ out,
                int B, int nJetBlocks) {
    if ((int)blockIdx.x < nJetBlocks) {
        // ================= jet: 2 events per warp, n=10 qubits =================
        // Amplitude index (10 bits): lane bits 0..3 (sub) = trash wires 9..6;
        // register bits r0..r5 = latent wires 5..0. Lane bit 4 = event select.
        int warpId = blockIdx.x * 2 + (threadIdx.x >> 5);
        if (warpId * 2 >= B) return;
        int lane = threadIdx.x & 31;
        int sub  = lane & 15;
        int half = lane >> 4;
        int event = warpId * 2 + half;
        int evc = event < B ? event : B - 1;        // clamp loads for odd B
        const float* xr = x + (size_t)evc * 56;

        // Per-wire encoding column: lanes sub 0..9 of each half compute; values
        // broadcast on demand via width-16 shfl.
        int kk = sub < 10 ? sub : 0;
        float2 myu0, myu1;
        wire_u(xr[26 + kk], xr[36 + kk], xr[46 + kk], myu0, myu1);

        // Lane-bit part of the tensor product: sub bit m <-> trash wire 9-m.
        float2 pl = make_float2(1.f, 0.f);
#pragma unroll
        for (int m = 0; m < 4; m++) {
            int w = 9 - m;
            float2 b0 = bc16(myu0.x, myu0.y, w);
            float2 b1 = bc16(myu1.x, myu1.y, w);
            float2 sel = ((sub >> m) & 1) ? b1 : b0;
            pl = cmul(pl, sel);
        }

        bool p1 = (__popc(sub) & 1) != 0;   // parity of trash bits

        // Register-bit part via doubling: reg bit j <-> latent wire 5-j.
        // Depth-0 perm1 (flip all latent bits if p1) folded in: u roles swap.
        ull a[64];
        a[0] = pack2(pl.x, pl.y);
#pragma unroll
        for (int j = 0; j < 6; j++) {
            int w = 5 - j;
            float2 b0 = bc16(myu0.x, myu0.y, w);
            float2 b1 = bc16(myu1.x, myu1.y, w);
            float2 f0 = p1 ? b1 : b0;
            float2 f1 = p1 ? b0 : b1;
#pragma unroll
            for (int t = 0; t < (1 << j); t++) {
                float2 at = unpack2(a[t]);
                float2 hi = cmul(at, f1);
                float2 lo = cmul(at, f0);
                a[t + (1 << j)] = pack2(hi.x, hi.y);
                a[t]            = pack2(lo.x, lo.y);
            }
        }

#pragma unroll 1
        for (int d = 0; d < 4; d++) {
            // perm1 (d>0; depth-0 folded into encoding): flip all 6 register
            // (latent) bits if p1 -> conditional register-pair swap.
            if (d) {
#pragma unroll
                for (int r = 0; r < 32; r++) {
                    ull t0 = a[r], t1 = a[63 - r];
                    a[r]      = p1 ? t1 : t0;
                    a[63 - r] = p1 ? t0 : t1;
                }
            }
            // RY(jet_w[d*10+k]) on wire k, tau-factorized (scale deferred).
#pragma unroll
            for (int k = 0; k < 10; k++) {
                float tau = g_tau[d * 10 + k];
                if (k < 6) {                     // register bit j = 5-k
                    int m = 1 << (5 - k);
                    ull tq = pack2(tau, tau), ntq = pack2(-tau, -tau);
#pragma unroll
                    for (int r = 0; r < 64; r++) {
                        if (!(r & m)) {
                            int r1 = r | m;
                            ull a0 = a[r];
                            a[r]  = f2fma(ntq, a[r1], a0);
                            a[r1] = f2fma(tq, a0, a[r1]);
                        }
                    }
                } else {                         // lane bit (9-k): shfl pairing
                    int mb = 1 << (9 - k);
                    float tt = (sub & mb) ? tau : -tau;
                    ull t2 = pack2(tt, tt);
#pragma unroll
                    for (int r = 0; r < 64; r++) {
                        ull p = __shfl_xor_sync(FULL, a[r], mb);
                        a[r] = f2fma(t2, p, a[r]);
                    }
                }
            }
            // perm2: flip trash (lane) bits where popc(r) odd. Skipped on the
            // final depth (folded into the <Z> sign as S_even - S_odd).
            if (d != 3) {
#pragma unroll
                for (int r = 0; r < 64; r++) {
                    if (__popc(r) & 1)
                        a[r] = __shfl_xor_sync(FULL, a[r], 15);
                }
            }
        }

        // <Z> on trash wires 6..9 (sub bits 3..0), final perm2 + global scale
        // absorbed: Z_b = sign_b(sub) * (S_even - S_odd) * (prod cos)^2.
        ull ae = pack2(0.f, 0.f), ao = pack2(0.f, 0.f);
#pragma unroll
        for (int r = 0; r < 64; r++) {
            if (__popc(r) & 1) ao = f2fma(a[r], a[r], ao);
            else               ae = f2fma(a[r], a[r], ae);
        }
        float2 fe = unpack2(ae), fo = unpack2(ao);
        float sd = ((fe.x + fe.y) - (fo.x + fo.y)) * g_scale[0];
#pragma unroll
        for (int j = 0; j < 4; j++) {
            int bit = 3 - j;                 // wire 6+j -> sub bit 3-j
            float v = ((sub >> bit) & 1) ? -sd : sd;
#pragma unroll
            for (int off = 8; off >= 1; off >>= 1)
                v += __shfl_xor_sync(FULL, v, off);
            if (sub == 0 && event < B)
                out[(size_t)5 * B + (size_t)event * 4 + j] = v;
        }
    } else {
        // ---------------- met + ele + mu: one thread per event ----------------
        int e = (blockIdx.x - nJetBlocks) * 64 + threadIdx.x;
        if (e >= B) return;
        const float* xr = x + (size_t)e * 56;

        {   // met (n=1): <Z> = cos(w)cos(pt) - sin(w)sin(pt)cos(phi)
            float sp, cp;
            __sincosf(xr[0], &sp, &cp);
            float cf = __cosf(xr[1]);
            out[e] = g_met[1] * cp - g_met[0] * sp * cf;
        }
        float o0, o1;
        sim4(xr, 2, 6, 10, &g_tau[40], g_scale[1], o0, o1);
        out[(size_t)B + (size_t)e * 2 + 0] = o0;
        out[(size_t)B + (size_t)e * 2 + 1] = o1;
        sim4(xr, 14, 18, 22, &g_tau[44], g_scale[2], o0, o1);
        out[(size_t)3 * B + (size_t)e * 2 + 0] = o0;
        out[(size_t)3 * B + (size_t)e * 2 + 1] = o1;
    }
}

extern "C" void kernel_launch(void* const* d_in, const int* in_sizes, int n_in,
                              void* d_out, int out_size) {
    const float* x     = (const float*)d_in[0];
    const float* met_w = (const float*)d_in[1];
    const float* ele_w = (const float*)d_in[2];
    const float* mu_w  = (const float*)d_in[3];
    const float* jet_w = (const float*)d_in[4];
    int B = in_sizes[0] / 56;
    int nJetBlocks = (B + 3) / 4;          // 2 warps/block, 2 events/warp
    int nSmallBlocks = (B + 63) / 64;      // 1 thread/event for met/ele/mu
    prep_kernel<<<1, 32>>>(met_w, ele_w, mu_w, jet_w);
    qae_kernel<<<nJetBlocks + nSmallBlocks, 64>>>(
        x, (float*)d_out, B, nJetBlocks);
}